// round 14
// baseline (speedup 1.0000x reference)
#include <cuda_runtime.h>
#include <cuda_fp16.h>
#include <math.h>
#include <stdint.h>

#define Bb 512
#define Ff 64
#define Tt 64
#define Hh 512
#define Kk 4
#define NN (3 * Hh)   // 1536
#define NCTA_PERSIST 128

// ---------------- scratch (static device globals; no allocation) ----------------
__device__ __align__(16) __half g_d[(size_t)Tt * Bb * Ff];        // data fp16 [t][b][f]
__device__ __align__(16) __half g_fcW[(size_t)Kk * Hh * Ff];
__device__ __align__(16) __half g_x[(size_t)Kk * Tt * Bb * Hh];   // x fp16
__device__ __align__(16) __half g_Wih[(size_t)Kk * NN * Hh];
__device__ __align__(16) __half g_Whhc[(size_t)Kk * NN * Hh];     // Whh, composite row order
// ping-pong hidden state (read buf t&1, write buf (t&1)^1)
__device__ __align__(16) __half g_hf[2 * (size_t)Kk * Bb * Hh];
__device__ __align__(16) float g_h[2 * (size_t)Kk * Bb * Hh];
__device__ __align__(16) float g_gi[(size_t)Kk * Tt * Bb * NN];   // [k][(t,b)][3H] plain
__device__ __align__(16) float g_hs[(size_t)Kk * Tt * Bb * Hh];   // [k][t][b][h]
__device__ unsigned g_bar = 0;                                    // grid barrier (monotonic)

// ---------------- helpers ----------------
__device__ __forceinline__ uint32_t smem_u32(const void* p) {
    uint32_t a;
    asm("{ .reg .u64 t; cvta.to.shared.u64 t, %1; cvt.u32.u64 %0, t; }" : "=r"(a) : "l"(p));
    return a;
}
__device__ __forceinline__ void cp16(uint32_t saddr, const void* g) {
    asm volatile("cp.async.cg.shared.global [%0], [%1], 16;" :: "r"(saddr), "l"(g));
}
__device__ __forceinline__ void cp_commit() {
    asm volatile("cp.async.commit_group;" ::: "memory");
}
template <int N> __device__ __forceinline__ void cp_wait() {
    asm volatile("cp.async.wait_group %0;" :: "n"(N) : "memory");
}
__device__ __forceinline__ void ldsm_x4(uint32_t a, uint32_t* r) {
    asm volatile("ldmatrix.sync.aligned.m8n8.x4.shared.b16 {%0,%1,%2,%3}, [%4];"
                 : "=r"(r[0]), "=r"(r[1]), "=r"(r[2]), "=r"(r[3]) : "r"(a));
}
__device__ __forceinline__ void mma16816(float* d, const uint32_t* a, const uint32_t* b) {
    asm volatile(
        "mma.sync.aligned.m16n8k16.row.col.f32.f16.f16.f32 "
        "{%0,%1,%2,%3}, {%4,%5,%6,%7}, {%8,%9}, {%0,%1,%2,%3};"
        : "+f"(d[0]), "+f"(d[1]), "+f"(d[2]), "+f"(d[3])
        : "r"(a[0]), "r"(a[1]), "r"(a[2]), "r"(a[3]), "r"(b[0]), "r"(b[1]));
}
__device__ __forceinline__ float sigm(float x) { return 1.f / (1.f + expf(-x)); }

// swizzle for 64B rows (k-chunk 32 fp16): chunk (0..3) ^= (row>>1)&3
__device__ __forceinline__ uint32_t swz64(int r, int c) {
    return (uint32_t)(r * 64 + ((c ^ ((r >> 1) & 3)) << 4));
}
// swizzle for 32B rows (k-chunk 16 fp16): chunk (0..1) ^= (row>>2)&1
__device__ __forceinline__ uint32_t swz32(int r, int c) {
    return (uint32_t)(r * 32 + ((c ^ ((r >> 2) & 1)) << 4));
}
// composite col j = 24q + 8g + s  ->  original W row g*512 + 8q + s
__device__ __forceinline__ int c2o(int j) {
    return ((j >> 3) % 3) * Hh + (j / 24) * 8 + (j & 7);
}

// grid barrier: monotonic counter, no reset race; counter stays ≡0 mod NCTA across calls
__device__ __forceinline__ void grid_sync() {
    __syncthreads();
    if (threadIdx.x == 0) {
        __threadfence();
        unsigned old = atomicAdd(&g_bar, 1u);
        unsigned need = (old / NCTA_PERSIST + 1u) * NCTA_PERSIST;
        while (*((volatile unsigned*)&g_bar) < need) {}
        __threadfence();
    }
    __syncthreads();
}

// ---------------- data transpose: [B,F,T] -> fp16 [T,B,F] ----------------
__global__ void transpose_data(const float* __restrict__ data) {
    int idx = blockIdx.x * blockDim.x + threadIdx.x;
    if (idx >= Tt * Bb * Ff) return;
    int f = idx % Ff;
    int b = (idx / Ff) % Bb;
    int t = idx / (Ff * Bb);
    g_d[idx] = __float2half(data[(size_t)b * Ff * Tt + (size_t)f * Tt + t]);
}

// ---------------- weight conversion: Wih plain fp16, Whh composite fp16, fcW fp16 ----
__global__ void convert_w(const float* __restrict__ Wih, const float* __restrict__ Whh,
                          const float* __restrict__ fcW) {
    const int NW = Kk * NN * Hh;
    const int NF = Kk * Hh * Ff;
    int idx = blockIdx.x * 256 + threadIdx.x;
    if (idx < NW) {
        g_Wih[idx] = __float2half(Wih[idx]);
    } else if (idx < 2 * NW) {
        // destination-indexed composite permutation of Whh rows
        int i = idx - NW;
        int k = i / (NN * Hh);
        int rem = i - k * (NN * Hh);
        int j = rem / Hh;           // composite row
        int col = rem - j * Hh;
        g_Whhc[i] = __float2half(Whh[((size_t)k * NN + c2o(j)) * Hh + col]);
    } else if (idx < 2 * NW + NF) {
        g_fcW[idx - 2 * NW] = __float2half(fcW[idx - 2 * NW]);
    }
}

// ---------------- h init -> buffer 0 ----------------
__global__ void init_h_kernel(const float* __restrict__ init) {
    int idx = blockIdx.x * 256 + threadIdx.x;   // K*B*H
    float v = init[idx % (Bb * Hh)];
    g_h[idx] = v;
    g_hf[idx] = __float2half(v);
}

// ---------------- proj: fp16 HMMA, M128 x N128, K=64 -> relu -> g_x ----------------
__global__ void __launch_bounds__(256, 2) proj_hmma(const float* __restrict__ fcB) {
    __shared__ __align__(16) char smem[16384];   // 2 stages x (A 4K + B 4K)
    uint32_t sb = smem_u32(smem);
    int tid = threadIdx.x, wid = tid >> 5, lane = tid & 31;
    int z = blockIdx.z;
    int n0 = blockIdx.x * 128, m0 = blockIdx.y * 128;
    int warp_m = wid >> 2, warp_n = wid & 3;      // warp tile 64 x 32
    int t = m0 >> 9, b0 = m0 & 511;
    int tt = (z < 2) ? t : (Tt - 1 - t);

    const __half* A = g_d + ((size_t)tt * Bb + b0) * Ff;
    const __half* Bw = g_fcW + (size_t)z * Hh * Ff;

    float acc[4][4][4];
#pragma unroll
    for (int i = 0; i < 4; i++)
#pragma unroll
        for (int j = 0; j < 4; j++)
#pragma unroll
            for (int q = 0; q < 4; q++) acc[i][j][q] = 0.f;

    auto load_stage = [&](int s, int k0) {
        uint32_t st = sb + s * 8192;
#pragma unroll
        for (int i = 0; i < 2; i++) {
            int idx = tid + i * 256;           // 0..511
            bool isA = idx < 256;
            int li = idx & 255;
            int r = li >> 1, c = li & 1;
            cp16(st + (isA ? 0 : 4096) + swz32(r, c),
                 (isA ? A : Bw) + (size_t)(isA ? r : n0 + r) * Ff + k0 + c * 8);
        }
        cp_commit();
    };

    load_stage(0, 0);
    int cfr = lane >> 4;
    for (int kc = 0; kc < 4; kc++) {
        if (kc + 1 < 4) { load_stage((kc + 1) & 1, (kc + 1) * 16); cp_wait<1>(); }
        else cp_wait<0>();
        __syncthreads();
        uint32_t st = sb + (uint32_t)(kc & 1) * 8192;
        uint32_t a_f[4][4], b_f[4][2];
#pragma unroll
        for (int mi = 0; mi < 4; mi++) {
            int rA = warp_m * 64 + mi * 16 + (lane & 15);
            ldsm_x4(st + swz32(rA, cfr), a_f[mi]);
        }
#pragma unroll
        for (int nj = 0; nj < 2; nj++) {
            int rB = warp_n * 32 + nj * 16 + (lane & 15);
            uint32_t r4[4];
            ldsm_x4(st + 4096 + swz32(rB, cfr), r4);
            b_f[2 * nj][0] = r4[0]; b_f[2 * nj][1] = r4[2];
            b_f[2 * nj + 1][0] = r4[1]; b_f[2 * nj + 1][1] = r4[3];
        }
#pragma unroll
        for (int mi = 0; mi < 4; mi++)
#pragma unroll
            for (int ni = 0; ni < 4; ni++)
                mma16816(acc[mi][ni], a_f[mi], b_f[ni]);
        __syncthreads();
    }

    int lane4 = lane >> 2;
    int cp2 = 2 * (lane & 3);
    const float* bz = fcB + (size_t)z * Hh;
#pragma unroll
    for (int mi = 0; mi < 4; mi++)
#pragma unroll
        for (int v = 0; v < 2; v++) {
            int rl = warp_m * 64 + mi * 16 + lane4 + 8 * v;
            size_t rowoff = (((size_t)z * Tt + t) * Bb + (b0 + rl)) * Hh;
#pragma unroll
            for (int ni = 0; ni < 4; ni++) {
                int h = n0 + warp_n * 32 + ni * 8 + cp2;
                int q = 2 * v;
                __half2 hv;
                hv.x = __float2half(fmaxf(acc[mi][ni][q] + bz[h], 0.f));
                hv.y = __float2half(fmaxf(acc[mi][ni][q + 1] + bz[h + 1], 0.f));
                *(__half2*)(g_x + rowoff + h) = hv;
            }
        }
}

// ---------------- gi GEMM: fp16, CTA 128x128, warp 32x64, k-chunk 32, 3 stages ------
__global__ void __launch_bounds__(256, 1) gemm_gi(const float* __restrict__ biasb) {
    __shared__ __align__(16) char smem[49152];   // 3 stages x (A 8K + B 8K)
    uint32_t sb = smem_u32(smem);

    int tid = threadIdx.x, wid = tid >> 5, lane = tid & 31;
    int z = blockIdx.z;
    int n0 = blockIdx.x * 128, m0 = blockIdx.y * 128;
    int warp_m = wid >> 1;     // 4 warps over M (32 rows each)
    int warp_n = wid & 1;      // 2 warps over N (64 cols each)

    const __half* A = g_x + (size_t)z * Tt * Bb * Hh;
    const __half* Bw = g_Wih + (size_t)z * NN * Hh;
    float* C = g_gi + (size_t)z * Tt * Bb * NN;
    const float* bias = biasb + (size_t)z * NN;

    float acc[2][8][4];
#pragma unroll
    for (int i = 0; i < 2; i++)
#pragma unroll
        for (int j = 0; j < 8; j++)
#pragma unroll
            for (int q = 0; q < 4; q++) acc[i][j][q] = 0.f;

    auto load_stage = [&](int s, int k0) {
        uint32_t st = sb + (uint32_t)s * 16384;
#pragma unroll
        for (int i = 0; i < 4; i++) {
            int idx = tid + i * 256;            // 0..1023
            bool isA = idx < 512;
            int li = idx & 511;
            int r = li >> 2, c = li & 3;
            cp16(st + (isA ? 0 : 8192) + swz64(r, c),
                 (isA ? A : Bw) + (size_t)((isA ? m0 : n0) + r) * Hh + k0 + c * 8);
        }
        cp_commit();
    };

    load_stage(0, 0);
    load_stage(1, 32);

    for (int kc = 0; kc < 16; kc++) {
        if (kc + 2 < 16) { load_stage((kc + 2) % 3, (kc + 2) * 32); cp_wait<2>(); }
        else if (kc + 1 < 16) cp_wait<1>();
        else cp_wait<0>();
        __syncthreads();

        uint32_t st = sb + (uint32_t)(kc % 3) * 16384;
#pragma unroll
        for (int ks = 0; ks < 2; ks++) {
            uint32_t a_f[2][4], b_f[8][2];
            int chunk = ks * 2 + (lane >> 4);
#pragma unroll
            for (int mi = 0; mi < 2; mi++) {
                int rr = warp_m * 32 + mi * 16 + (lane & 15);
                ldsm_x4(st + swz64(rr, chunk), a_f[mi]);
            }
#pragma unroll
            for (int nj = 0; nj < 4; nj++) {
                int rr = warp_n * 64 + nj * 16 + (lane & 15);
                uint32_t r4[4];
                ldsm_x4(st + 8192 + swz64(rr, chunk), r4);
                b_f[2 * nj][0] = r4[0]; b_f[2 * nj][1] = r4[2];
                b_f[2 * nj + 1][0] = r4[1]; b_f[2 * nj + 1][1] = r4[3];
            }
#pragma unroll
            for (int mi = 0; mi < 2; mi++)
#pragma unroll
                for (int ni = 0; ni < 8; ni++)
                    mma16816(acc[mi][ni], a_f[mi], b_f[ni]);
        }
        __syncthreads();
    }

#pragma unroll
    for (int mi = 0; mi < 2; mi++) {
        int row = m0 + warp_m * 32 + mi * 16 + (lane >> 2);
#pragma unroll
        for (int ni = 0; ni < 8; ni++) {
            int col = n0 + warp_n * 64 + ni * 8 + 2 * (lane & 3);
            float2 o0, o1;
            o0.x = acc[mi][ni][0] + bias[col];
            o0.y = acc[mi][ni][1] + bias[col + 1];
            o1.x = acc[mi][ni][2] + bias[col];
            o1.y = acc[mi][ni][3] + bias[col + 1];
            *(float2*)(C + (size_t)row * NN + col) = o0;
            *(float2*)(C + (size_t)(row + 8) * NN + col) = o1;
        }
    }
}

// ---------------- persistent recurrence: 64 fused steps, grid barrier between -------
// 128 CTAs: bx -> (n-block 0..7, m-block 0..3, cell 0..3). CTA tile M128 x N192 comp.
// Per step: gh GEMM (composite Whh) + in-register GRU gates; ping-pong h buffers.
// Cross-SM coherence: A via cp.async.cg (L2 path), h_prev via __ldcg, stores->L2.
__global__ void __launch_bounds__(256, 1) persistent_steps(const float* __restrict__ bhh) {
    __shared__ __align__(16) char smem[40960];   // 2 stages x (A 8K + B 12K)
    uint32_t sb = smem_u32(smem);

    int tid = threadIdx.x, wid = tid >> 5, lane = tid & 31;
    int bx = blockIdx.x;
    int nb = bx & 7, mb = (bx >> 3) & 3, zz = bx >> 5;
    int n0 = nb * 192, m0 = mb * 128;
    int warp_m = wid >> 2, warp_n = wid & 3;      // warp tile 64 x 48

    const __half* Bw = g_Whhc + (size_t)zz * NN * Hh;
    const float* giK = g_gi + (size_t)zz * Tt * Bb * NN;
    const float* bz = bhh + (size_t)zz * NN;

    int lane4 = lane >> 2;
    int cp2 = 2 * (lane & 3);

    for (int t = 0; t < Tt; t++) {
        int rb = t & 1, wb = rb ^ 1;
        const __half* A = g_hf + ((size_t)rb * Kk + zz) * Bb * Hh;

        float acc[4][6][4];
#pragma unroll
        for (int i = 0; i < 4; i++)
#pragma unroll
            for (int j = 0; j < 6; j++)
#pragma unroll
                for (int q = 0; q < 4; q++) acc[i][j][q] = 0.f;

        auto load_stage = [&](int s, int k0) {
            uint32_t st = sb + (uint32_t)s * 20480;
#pragma unroll
            for (int i = 0; i < 2; i++) {          // A: 512 chunks
                int idx = tid + i * 256;
                int r = idx >> 2, c = idx & 3;
                cp16(st + swz64(r, c), A + (size_t)(m0 + r) * Hh + k0 + c * 8);
            }
#pragma unroll
            for (int i = 2; i < 5; i++) {          // B: 768 chunks
                int li = tid + (i - 2) * 256;
                int r = li >> 2, c = li & 3;
                cp16(st + 8192 + swz64(r, c), Bw + (size_t)(n0 + r) * Hh + k0 + c * 8);
            }
            cp_commit();
        };

        load_stage(0, 0);

        for (int kc = 0; kc < 16; kc++) {
            if (kc + 1 < 16) { load_stage((kc + 1) & 1, (kc + 1) * 32); cp_wait<1>(); }
            else cp_wait<0>();
            __syncthreads();

            uint32_t st = sb + (uint32_t)(kc & 1) * 20480;
#pragma unroll
            for (int ks = 0; ks < 2; ks++) {
                uint32_t a_f[4][4], b_f[6][2];
                int chunk = ks * 2 + (lane >> 4);
#pragma unroll
                for (int mi = 0; mi < 4; mi++) {
                    int rA = warp_m * 64 + mi * 16 + (lane & 15);
                    ldsm_x4(st + swz64(rA, chunk), a_f[mi]);
                }
#pragma unroll
                for (int nj = 0; nj < 3; nj++) {
                    int rB = warp_n * 48 + nj * 16 + (lane & 15);
                    uint32_t r4[4];
                    ldsm_x4(st + 8192 + swz64(rB, chunk), r4);
                    b_f[2 * nj][0] = r4[0]; b_f[2 * nj][1] = r4[2];
                    b_f[2 * nj + 1][0] = r4[1]; b_f[2 * nj + 1][1] = r4[3];
                }
#pragma unroll
                for (int mi = 0; mi < 4; mi++)
#pragma unroll
                    for (int ni = 0; ni < 6; ni++)
                        mma16816(acc[mi][ni], a_f[mi], b_f[ni]);
            }
            __syncthreads();
        }

        // ---- fused GRU gates (in registers) ----
#pragma unroll
        for (int tr = 0; tr < 2; tr++) {
            int jr = n0 + warp_n * 48 + tr * 24;
            int h0e = (jr / 24) * 8 + cp2;
            float br0 = bz[h0e],          br1 = bz[h0e + 1];
            float bz0 = bz[Hh + h0e],     bz1 = bz[Hh + h0e + 1];
            float bn0 = bz[2 * Hh + h0e], bn1 = bz[2 * Hh + h0e + 1];
#pragma unroll
            for (int mi = 0; mi < 4; mi++)
#pragma unroll
                for (int v = 0; v < 2; v++) {
                    int b = m0 + warp_m * 64 + mi * 16 + lane4 + 8 * v;
                    const float* gi = giK + ((size_t)t * Bb + b) * NN;
                    float2 gir = *(const float2*)(gi + h0e);
                    float2 giz = *(const float2*)(gi + Hh + h0e);
                    float2 gin = *(const float2*)(gi + 2 * Hh + h0e);
                    float2 hp = __ldcg((const float2*)(
                        g_h + (((size_t)rb * Kk + zz) * Bb + b) * Hh + h0e));
                    int q = 2 * v;
                    float R0 = sigm(gir.x + acc[mi][3 * tr + 0][q] + br0);
                    float Z0 = sigm(giz.x + acc[mi][3 * tr + 1][q] + bz0);
                    float N0 = tanhf(gin.x + R0 * (acc[mi][3 * tr + 2][q] + bn0));
                    float hn0 = (1.f - Z0) * N0 + Z0 * hp.x;
                    float R1 = sigm(gir.y + acc[mi][3 * tr + 0][q + 1] + br1);
                    float Z1 = sigm(giz.y + acc[mi][3 * tr + 1][q + 1] + bz1);
                    float N1 = tanhf(gin.y + R1 * (acc[mi][3 * tr + 2][q + 1] + bn1));
                    float hn1 = (1.f - Z1) * N1 + Z1 * hp.y;

                    size_t hoff = (((size_t)wb * Kk + zz) * Bb + b) * Hh + h0e;
                    *(float2*)(g_h + hoff) = make_float2(hn0, hn1);
                    *(float2*)(g_hs + (((size_t)zz * Tt + t) * Bb + b) * Hh + h0e) =
                        make_float2(hn0, hn1);
                    __half2 hv;
                    hv.x = __float2half(hn0);
                    hv.y = __float2half(hn1);
                    *(__half2*)(g_hf + hoff) = hv;
                }
        }

        grid_sync();
    }
}

// ---------------- output heads ----------------
__global__ void out_kernel(const float* __restrict__ Wout,
                           const float* __restrict__ bout,
                           float* __restrict__ out) {
    int warp = threadIdx.x >> 5;
    int lane = threadIdx.x & 31;
    int oid = blockIdx.x * 8 + warp;
    int pair = oid >> 15;
    int rem = oid & 32767;
    int b = rem >> 6;
    int t = rem & 63;
    const float* hf = g_hs + (((size_t)pair * Tt + t) * Bb + b) * Hh;
    const float* hb = g_hs + (((size_t)(pair + 2) * Tt + (Tt - 1 - t)) * Bb + b) * Hh;
    const float* w = Wout + pair * Hh;
    float s = 0.f;
    for (int i0 = lane * 4; i0 < Hh; i0 += 128) {
        float4 f = *(const float4*)(hf + i0);
        float4 g = *(const float4*)(hb + i0);
        float4 wv = *(const float4*)(w + i0);
        s += (f.x + g.x) * wv.x + (f.y + g.y) * wv.y +
             (f.z + g.z) * wv.z + (f.w + g.w) * wv.w;
    }
#pragma unroll
    for (int o = 16; o; o >>= 1) s += __shfl_xor_sync(0xffffffffu, s, o);
    if (lane == 0) out[(size_t)pair * Bb * Tt + b * Tt + t] = s + bout[pair];
}

// ---------------- launch (kernel launches ONLY) ----------------
extern "C" void kernel_launch(void* const* d_in, const int* in_sizes, int n_in,
                              void* d_out, int out_size) {
    const float* data     = (const float*)d_in[0];
    const float* init     = (const float*)d_in[1];
    const float* fc_in_W  = (const float*)d_in[2];
    const float* fc_in_b  = (const float*)d_in[3];
    const float* Wih      = (const float*)d_in[4];
    const float* Whh      = (const float*)d_in[5];
    const float* bih      = (const float*)d_in[6];
    const float* bhh      = (const float*)d_in[7];
    const float* fc_out_W = (const float*)d_in[8];
    const float* fc_out_b = (const float*)d_in[9];
    float* out = (float*)d_out;

    transpose_data<<<(Tt * Bb * Ff) / 256, 256>>>(data);
    convert_w<<<(2 * Kk * NN * Hh + Kk * Hh * Ff) / 256, 256>>>(Wih, Whh, fc_in_W);

    // proj (fp16 HMMA): M = T*B per cell, N = 512, K = 64
    proj_hmma<<<dim3(Hh / 128, (Tt * Bb) / 128, Kk), 256>>>(fc_in_b);

    // gi = xseq @ Wih^T + bih : M = T*B = 32768
    gemm_gi<<<dim3(NN / 128, (Tt * Bb) / 128, Kk), 256>>>(bih);

    init_h_kernel<<<(Kk * Bb * Hh) / 256, 256>>>(init);

    // all 64 recurrence steps in ONE persistent kernel (128 co-resident CTAs)
    persistent_steps<<<NCTA_PERSIST, 256>>>(bhh);

    out_kernel<<<(2 * Bb * Tt) / 8, 256>>>(fc_out_W, fc_out_b, out);
}

// round 15
// speedup vs baseline: 1.8303x; 1.8303x over previous
#include <cuda_runtime.h>
#include <cuda_fp16.h>
#include <math.h>
#include <stdint.h>

#define Bb 512
#define Ff 64
#define Tt 64
#define Hh 512
#define Kk 4
#define NN (3 * Hh)   // 1536

// ---------------- scratch (static device globals; no allocation) ----------------
__device__ __align__(16) __half g_d[(size_t)Tt * Bb * Ff];        // data fp16 [t][b][f]
__device__ __align__(16) __half g_fcW[(size_t)Kk * Hh * Ff];
__device__ __align__(16) __half g_x[(size_t)Kk * Tt * Bb * Hh];   // x fp16
__device__ __align__(16) __half g_Wih[(size_t)Kk * NN * Hh];
__device__ __align__(16) __half g_Whhc[(size_t)Kk * NN * Hh];     // Whh, composite row order
// ping-pong hidden state (read buf t&1, write buf (t&1)^1)
__device__ __align__(16) __half g_hf[2 * (size_t)Kk * Bb * Hh];
__device__ __align__(16) float g_h[2 * (size_t)Kk * Bb * Hh];
__device__ __align__(16) float g_gi[(size_t)Kk * Tt * Bb * NN];   // [k][(t,b)][3H] plain
__device__ __align__(16) float g_hs[(size_t)Kk * Tt * Bb * Hh];   // [k][t][b][h]

// ---------------- helpers ----------------
__device__ __forceinline__ uint32_t smem_u32(const void* p) {
    uint32_t a;
    asm("{ .reg .u64 t; cvta.to.shared.u64 t, %1; cvt.u32.u64 %0, t; }" : "=r"(a) : "l"(p));
    return a;
}
__device__ __forceinline__ void cp16(uint32_t saddr, const void* g) {
    asm volatile("cp.async.cg.shared.global [%0], [%1], 16;" :: "r"(saddr), "l"(g));
}
__device__ __forceinline__ void cp_commit() {
    asm volatile("cp.async.commit_group;" ::: "memory");
}
template <int N> __device__ __forceinline__ void cp_wait() {
    asm volatile("cp.async.wait_group %0;" :: "n"(N) : "memory");
}
__device__ __forceinline__ void ldsm_x4(uint32_t a, uint32_t* r) {
    asm volatile("ldmatrix.sync.aligned.m8n8.x4.shared.b16 {%0,%1,%2,%3}, [%4];"
                 : "=r"(r[0]), "=r"(r[1]), "=r"(r[2]), "=r"(r[3]) : "r"(a));
}
__device__ __forceinline__ void mma16816(float* d, const uint32_t* a, const uint32_t* b) {
    asm volatile(
        "mma.sync.aligned.m16n8k16.row.col.f32.f16.f16.f32 "
        "{%0,%1,%2,%3}, {%4,%5,%6,%7}, {%8,%9}, {%0,%1,%2,%3};"
        : "+f"(d[0]), "+f"(d[1]), "+f"(d[2]), "+f"(d[3])
        : "r"(a[0]), "r"(a[1]), "r"(a[2]), "r"(a[3]), "r"(b[0]), "r"(b[1]));
}
__device__ __forceinline__ float sigm(float x) { return 1.f / (1.f + expf(-x)); }

// swizzle for 64B rows (k-chunk 32 fp16): chunk (0..3) ^= (row>>1)&3
__device__ __forceinline__ uint32_t swz64(int r, int c) {
    return (uint32_t)(r * 64 + ((c ^ ((r >> 1) & 3)) << 4));
}
// swizzle for 32B rows (k-chunk 16 fp16): chunk (0..1) ^= (row>>2)&1
__device__ __forceinline__ uint32_t swz32(int r, int c) {
    return (uint32_t)(r * 32 + ((c ^ ((r >> 2) & 1)) << 4));
}
// composite col j = 24q + 8g + s  ->  original W row g*512 + 8q + s
__device__ __forceinline__ int c2o(int j) {
    return ((j >> 3) % 3) * Hh + (j / 24) * 8 + (j & 7);
}

// ---------------- data transpose: [B,F,T] -> fp16 [T,B,F] ----------------
__global__ void transpose_data(const float* __restrict__ data) {
    int idx = blockIdx.x * blockDim.x + threadIdx.x;
    if (idx >= Tt * Bb * Ff) return;
    int f = idx % Ff;
    int b = (idx / Ff) % Bb;
    int t = idx / (Ff * Bb);
    g_d[idx] = __float2half(data[(size_t)b * Ff * Tt + (size_t)f * Tt + t]);
}

// ---------------- weight conversion: Wih plain fp16, Whh composite fp16, fcW fp16 ----
__global__ void convert_w(const float* __restrict__ Wih, const float* __restrict__ Whh,
                          const float* __restrict__ fcW) {
    const int NW = Kk * NN * Hh;
    const int NF = Kk * Hh * Ff;
    int idx = blockIdx.x * 256 + threadIdx.x;
    if (idx < NW) {
        g_Wih[idx] = __float2half(Wih[idx]);
    } else if (idx < 2 * NW) {
        // destination-indexed composite permutation of Whh rows
        int i = idx - NW;
        int k = i / (NN * Hh);
        int rem = i - k * (NN * Hh);
        int j = rem / Hh;           // composite row
        int col = rem - j * Hh;
        g_Whhc[i] = __float2half(Whh[((size_t)k * NN + c2o(j)) * Hh + col]);
    } else if (idx < 2 * NW + NF) {
        g_fcW[idx - 2 * NW] = __float2half(fcW[idx - 2 * NW]);
    }
}

// ---------------- h init -> buffer 0 ----------------
__global__ void init_h_kernel(const float* __restrict__ init) {
    int idx = blockIdx.x * 256 + threadIdx.x;   // K*B*H
    float v = init[idx % (Bb * Hh)];
    g_h[idx] = v;
    g_hf[idx] = __float2half(v);
}

// ---------------- proj: fp16 HMMA, M128 x N128, K=64 -> relu -> g_x ----------------
__global__ void __launch_bounds__(256, 2) proj_hmma(const float* __restrict__ fcB) {
    __shared__ __align__(16) char smem[16384];   // 2 stages x (A 4K + B 4K)
    uint32_t sb = smem_u32(smem);
    int tid = threadIdx.x, wid = tid >> 5, lane = tid & 31;
    int z = blockIdx.z;
    int n0 = blockIdx.x * 128, m0 = blockIdx.y * 128;
    int warp_m = wid >> 2, warp_n = wid & 3;      // warp tile 64 x 32
    int t = m0 >> 9, b0 = m0 & 511;
    int tt = (z < 2) ? t : (Tt - 1 - t);

    const __half* A = g_d + ((size_t)tt * Bb + b0) * Ff;
    const __half* Bw = g_fcW + (size_t)z * Hh * Ff;

    float acc[4][4][4];
#pragma unroll
    for (int i = 0; i < 4; i++)
#pragma unroll
        for (int j = 0; j < 4; j++)
#pragma unroll
            for (int q = 0; q < 4; q++) acc[i][j][q] = 0.f;

    auto load_stage = [&](int s, int k0) {
        uint32_t st = sb + s * 8192;
#pragma unroll
        for (int i = 0; i < 2; i++) {
            int idx = tid + i * 256;           // 0..511
            bool isA = idx < 256;
            int li = idx & 255;
            int r = li >> 1, c = li & 1;
            cp16(st + (isA ? 0 : 4096) + swz32(r, c),
                 (isA ? A : Bw) + (size_t)(isA ? r : n0 + r) * Ff + k0 + c * 8);
        }
        cp_commit();
    };

    load_stage(0, 0);
    int cfr = lane >> 4;
    for (int kc = 0; kc < 4; kc++) {
        if (kc + 1 < 4) { load_stage((kc + 1) & 1, (kc + 1) * 16); cp_wait<1>(); }
        else cp_wait<0>();
        __syncthreads();
        uint32_t st = sb + (uint32_t)(kc & 1) * 8192;
        uint32_t a_f[4][4], b_f[4][2];
#pragma unroll
        for (int mi = 0; mi < 4; mi++) {
            int rA = warp_m * 64 + mi * 16 + (lane & 15);
            ldsm_x4(st + swz32(rA, cfr), a_f[mi]);
        }
#pragma unroll
        for (int nj = 0; nj < 2; nj++) {
            int rB = warp_n * 32 + nj * 16 + (lane & 15);
            uint32_t r4[4];
            ldsm_x4(st + 4096 + swz32(rB, cfr), r4);
            b_f[2 * nj][0] = r4[0]; b_f[2 * nj][1] = r4[2];
            b_f[2 * nj + 1][0] = r4[1]; b_f[2 * nj + 1][1] = r4[3];
        }
#pragma unroll
        for (int mi = 0; mi < 4; mi++)
#pragma unroll
            for (int ni = 0; ni < 4; ni++)
                mma16816(acc[mi][ni], a_f[mi], b_f[ni]);
        __syncthreads();
    }

    int lane4 = lane >> 2;
    int cp2 = 2 * (lane & 3);
    const float* bz = fcB + (size_t)z * Hh;
#pragma unroll
    for (int mi = 0; mi < 4; mi++)
#pragma unroll
        for (int v = 0; v < 2; v++) {
            int rl = warp_m * 64 + mi * 16 + lane4 + 8 * v;
            size_t rowoff = (((size_t)z * Tt + t) * Bb + (b0 + rl)) * Hh;
#pragma unroll
            for (int ni = 0; ni < 4; ni++) {
                int h = n0 + warp_n * 32 + ni * 8 + cp2;
                int q = 2 * v;
                __half2 hv;
                hv.x = __float2half(fmaxf(acc[mi][ni][q] + bz[h], 0.f));
                hv.y = __float2half(fmaxf(acc[mi][ni][q + 1] + bz[h + 1], 0.f));
                *(__half2*)(g_x + rowoff + h) = hv;
            }
        }
}

// ---------------- gi GEMM: fp16, CTA 128x128, warp 32x64, k-chunk 32, 3 stages ------
__global__ void __launch_bounds__(256, 1) gemm_gi(const float* __restrict__ biasb) {
    __shared__ __align__(16) char smem[49152];   // 3 stages x (A 8K + B 8K)
    uint32_t sb = smem_u32(smem);

    int tid = threadIdx.x, wid = tid >> 5, lane = tid & 31;
    int z = blockIdx.z;
    int n0 = blockIdx.x * 128, m0 = blockIdx.y * 128;
    int warp_m = wid >> 1;     // 4 warps over M (32 rows each)
    int warp_n = wid & 1;      // 2 warps over N (64 cols each)

    const __half* A = g_x + (size_t)z * Tt * Bb * Hh;
    const __half* Bw = g_Wih + (size_t)z * NN * Hh;
    float* C = g_gi + (size_t)z * Tt * Bb * NN;
    const float* bias = biasb + (size_t)z * NN;

    float acc[2][8][4];
#pragma unroll
    for (int i = 0; i < 2; i++)
#pragma unroll
        for (int j = 0; j < 8; j++)
#pragma unroll
            for (int q = 0; q < 4; q++) acc[i][j][q] = 0.f;

    auto load_stage = [&](int s, int k0) {
        uint32_t st = sb + (uint32_t)s * 16384;
#pragma unroll
        for (int i = 0; i < 4; i++) {
            int idx = tid + i * 256;            // 0..1023
            bool isA = idx < 512;
            int li = idx & 511;
            int r = li >> 2, c = li & 3;
            cp16(st + (isA ? 0 : 8192) + swz64(r, c),
                 (isA ? A : Bw) + (size_t)((isA ? m0 : n0) + r) * Hh + k0 + c * 8);
        }
        cp_commit();
    };

    load_stage(0, 0);
    load_stage(1, 32);

    for (int kc = 0; kc < 16; kc++) {
        if (kc + 2 < 16) { load_stage((kc + 2) % 3, (kc + 2) * 32); cp_wait<2>(); }
        else if (kc + 1 < 16) cp_wait<1>();
        else cp_wait<0>();
        __syncthreads();

        uint32_t st = sb + (uint32_t)(kc % 3) * 16384;
#pragma unroll
        for (int ks = 0; ks < 2; ks++) {
            uint32_t a_f[2][4], b_f[8][2];
            int chunk = ks * 2 + (lane >> 4);
#pragma unroll
            for (int mi = 0; mi < 2; mi++) {
                int rr = warp_m * 32 + mi * 16 + (lane & 15);
                ldsm_x4(st + swz64(rr, chunk), a_f[mi]);
            }
#pragma unroll
            for (int nj = 0; nj < 4; nj++) {
                int rr = warp_n * 64 + nj * 16 + (lane & 15);
                uint32_t r4[4];
                ldsm_x4(st + 8192 + swz64(rr, chunk), r4);
                b_f[2 * nj][0] = r4[0]; b_f[2 * nj][1] = r4[2];
                b_f[2 * nj + 1][0] = r4[1]; b_f[2 * nj + 1][1] = r4[3];
            }
#pragma unroll
            for (int mi = 0; mi < 2; mi++)
#pragma unroll
                for (int ni = 0; ni < 8; ni++)
                    mma16816(acc[mi][ni], a_f[mi], b_f[ni]);
        }
        __syncthreads();
    }

#pragma unroll
    for (int mi = 0; mi < 2; mi++) {
        int row = m0 + warp_m * 32 + mi * 16 + (lane >> 2);
#pragma unroll
        for (int ni = 0; ni < 8; ni++) {
            int col = n0 + warp_n * 64 + ni * 8 + 2 * (lane & 3);
            float2 o0, o1;
            o0.x = acc[mi][ni][0] + bias[col];
            o0.y = acc[mi][ni][1] + bias[col + 1];
            o1.x = acc[mi][ni][2] + bias[col];
            o1.y = acc[mi][ni][3] + bias[col + 1];
            *(float2*)(C + (size_t)row * NN + col) = o0;
            *(float2*)(C + (size_t)(row + 8) * NN + col) = o1;
        }
    }
}

// ---------------- fused step: gh GEMM (composite Whh) + GRU gates ------------------
// CTA tile M=64 x N=192 (composite), k-chunk 32, 2 stages; warp tile 32x48.
// 2 CTAs/SM (32KB smem, ~110 regs); grid (8, 8, 4) = 256 CTAs.
// A = g_hf buf t&1, epilogue writes h into buf (t&1)^1 (ping-pong, no intra-launch WAR).
__global__ void __launch_bounds__(256, 2) gemm_step(const float* __restrict__ bhh, int t) {
    __shared__ __align__(16) char smem[32768];   // 2 stages x (A 4K + B 12K)
    uint32_t sb = smem_u32(smem);

    int tid = threadIdx.x, wid = tid >> 5, lane = tid & 31;
    int zz = blockIdx.z;
    int n0 = blockIdx.x * 192, m0 = blockIdx.y * 64;
    int warp_m = wid >> 2, warp_n = wid & 3;      // warp tile 32 x 48
    int rb = t & 1, wb = rb ^ 1;

    const __half* A = g_hf + ((size_t)rb * Kk + zz) * Bb * Hh;
    const __half* Bw = g_Whhc + (size_t)zz * NN * Hh;

    float acc[2][6][4];
#pragma unroll
    for (int i = 0; i < 2; i++)
#pragma unroll
        for (int j = 0; j < 6; j++)
#pragma unroll
            for (int q = 0; q < 4; q++) acc[i][j][q] = 0.f;

    // stage = A 256 chunks + B 768 chunks = 1024 / 256 thr = 4
    auto load_stage = [&](int s, int k0) {
        uint32_t st = sb + (uint32_t)s * 16384;
        {   // A: 256 chunks (64 rows x 4)
            int r = tid >> 2, c = tid & 3;
            cp16(st + swz64(r, c), A + (size_t)(m0 + r) * Hh + k0 + c * 8);
        }
#pragma unroll
        for (int i = 1; i < 4; i++) {          // B: 768 chunks (192 rows x 4)
            int li = tid + (i - 1) * 256;
            int r = li >> 2, c = li & 3;
            cp16(st + 4096 + swz64(r, c), Bw + (size_t)(n0 + r) * Hh + k0 + c * 8);
        }
        cp_commit();
    };

    load_stage(0, 0);

    for (int kc = 0; kc < 16; kc++) {
        if (kc + 1 < 16) { load_stage((kc + 1) & 1, (kc + 1) * 32); cp_wait<1>(); }
        else cp_wait<0>();
        __syncthreads();

        uint32_t st = sb + (uint32_t)(kc & 1) * 16384;
#pragma unroll
        for (int ks = 0; ks < 2; ks++) {
            uint32_t a_f[2][4], b_f[6][2];
            int chunk = ks * 2 + (lane >> 4);
#pragma unroll
            for (int mi = 0; mi < 2; mi++) {
                int rA = warp_m * 32 + mi * 16 + (lane & 15);
                ldsm_x4(st + swz64(rA, chunk), a_f[mi]);
            }
#pragma unroll
            for (int nj = 0; nj < 3; nj++) {
                int rB = warp_n * 48 + nj * 16 + (lane & 15);
                uint32_t r4[4];
                ldsm_x4(st + 4096 + swz64(rB, chunk), r4);
                b_f[2 * nj][0] = r4[0]; b_f[2 * nj][1] = r4[2];
                b_f[2 * nj + 1][0] = r4[1]; b_f[2 * nj + 1][1] = r4[3];
            }
#pragma unroll
            for (int mi = 0; mi < 2; mi++)
#pragma unroll
                for (int ni = 0; ni < 6; ni++)
                    mma16816(acc[mi][ni], a_f[mi], b_f[ni]);
        }
        __syncthreads();
    }

    // ---- fused GRU gates (in registers), plain gi/bias reads ----
    int lane4 = lane >> 2;
    int cp2 = 2 * (lane & 3);
    const float* giK = g_gi + (size_t)zz * Tt * Bb * NN;
    const float* bz = bhh + (size_t)zz * NN;
#pragma unroll
    for (int tr = 0; tr < 2; tr++) {
        int jr = n0 + warp_n * 48 + tr * 24;    // composite col of this triple's r-tile
        int h0e = (jr / 24) * 8 + cp2;          // h index pair handled by this thread
        float br0 = bz[h0e],          br1 = bz[h0e + 1];
        float bz0 = bz[Hh + h0e],     bz1 = bz[Hh + h0e + 1];
        float bn0 = bz[2 * Hh + h0e], bn1 = bz[2 * Hh + h0e + 1];
#pragma unroll
        for (int mi = 0; mi < 2; mi++)
#pragma unroll
            for (int v = 0; v < 2; v++) {
                int b = m0 + warp_m * 32 + mi * 16 + lane4 + 8 * v;
                const float* gi = giK + ((size_t)t * Bb + b) * NN;
                float2 gir = *(const float2*)(gi + h0e);
                float2 giz = *(const float2*)(gi + Hh + h0e);
                float2 gin = *(const float2*)(gi + 2 * Hh + h0e);
                float2 hp = *(const float2*)(
                    g_h + (((size_t)rb * Kk + zz) * Bb + b) * Hh + h0e);
                int q = 2 * v;
                float R0 = sigm(gir.x + acc[mi][3 * tr + 0][q] + br0);
                float Z0 = sigm(giz.x + acc[mi][3 * tr + 1][q] + bz0);
                float N0 = tanhf(gin.x + R0 * (acc[mi][3 * tr + 2][q] + bn0));
                float hn0 = (1.f - Z0) * N0 + Z0 * hp.x;
                float R1 = sigm(gir.y + acc[mi][3 * tr + 0][q + 1] + br1);
                float Z1 = sigm(giz.y + acc[mi][3 * tr + 1][q + 1] + bz1);
                float N1 = tanhf(gin.y + R1 * (acc[mi][3 * tr + 2][q + 1] + bn1));
                float hn1 = (1.f - Z1) * N1 + Z1 * hp.y;

                size_t hoff = (((size_t)wb * Kk + zz) * Bb + b) * Hh + h0e;
                *(float2*)(g_h + hoff) = make_float2(hn0, hn1);
                *(float2*)(g_hs + (((size_t)zz * Tt + t) * Bb + b) * Hh + h0e) =
                    make_float2(hn0, hn1);
                __half2 hv;
                hv.x = __float2half(hn0);
                hv.y = __float2half(hn1);
                *(__half2*)(g_hf + hoff) = hv;
            }
    }
}

// ---------------- output heads ----------------
__global__ void out_kernel(const float* __restrict__ Wout,
                           const float* __restrict__ bout,
                           float* __restrict__ out) {
    int warp = threadIdx.x >> 5;
    int lane = threadIdx.x & 31;
    int oid = blockIdx.x * 8 + warp;
    int pair = oid >> 15;
    int rem = oid & 32767;
    int b = rem >> 6;
    int t = rem & 63;
    const float* hf = g_hs + (((size_t)pair * Tt + t) * Bb + b) * Hh;
    const float* hb = g_hs + (((size_t)(pair + 2) * Tt + (Tt - 1 - t)) * Bb + b) * Hh;
    const float* w = Wout + pair * Hh;
    float s = 0.f;
    for (int i0 = lane * 4; i0 < Hh; i0 += 128) {
        float4 f = *(const float4*)(hf + i0);
        float4 g = *(const float4*)(hb + i0);
        float4 wv = *(const float4*)(w + i0);
        s += (f.x + g.x) * wv.x + (f.y + g.y) * wv.y +
             (f.z + g.z) * wv.z + (f.w + g.w) * wv.w;
    }
#pragma unroll
    for (int o = 16; o; o >>= 1) s += __shfl_xor_sync(0xffffffffu, s, o);
    if (lane == 0) out[(size_t)pair * Bb * Tt + b * Tt + t] = s + bout[pair];
}

// ---------------- launch (kernel launches ONLY) ----------------
extern "C" void kernel_launch(void* const* d_in, const int* in_sizes, int n_in,
                              void* d_out, int out_size) {
    const float* data     = (const float*)d_in[0];
    const float* init     = (const float*)d_in[1];
    const float* fc_in_W  = (const float*)d_in[2];
    const float* fc_in_b  = (const float*)d_in[3];
    const float* Wih      = (const float*)d_in[4];
    const float* Whh      = (const float*)d_in[5];
    const float* bih      = (const float*)d_in[6];
    const float* bhh      = (const float*)d_in[7];
    const float* fc_out_W = (const float*)d_in[8];
    const float* fc_out_b = (const float*)d_in[9];
    float* out = (float*)d_out;

    transpose_data<<<(Tt * Bb * Ff) / 256, 256>>>(data);
    convert_w<<<(2 * Kk * NN * Hh + Kk * Hh * Ff) / 256, 256>>>(Wih, Whh, fc_in_W);

    // proj (fp16 HMMA): M = T*B per cell, N = 512, K = 64
    proj_hmma<<<dim3(Hh / 128, (Tt * Bb) / 128, Kk), 256>>>(fc_in_b);

    // gi = xseq @ Wih^T + bih : M = T*B = 32768
    gemm_gi<<<dim3(NN / 128, (Tt * Bb) / 128, Kk), 256>>>(bih);

    init_h_kernel<<<(Kk * Bb * Hh) / 256, 256>>>(init);

    for (int t = 0; t < Tt; t++) {
        // fused gh GEMM + gates: grid (8, 8, 4) = 256 CTAs, 2 CTAs/SM
        gemm_step<<<dim3(NN / 192, Bb / 64, Kk), 256>>>(bhh, t);
    }

    out_kernel<<<(2 * Bb * Tt) / 8, 256>>>(fc_out_W, fc_out_b, out);
}